// round 14
// baseline (speedup 1.0000x reference)
#include <cuda_runtime.h>
#include <cuda_fp16.h>
#include <cstdint>
#include <cstddef>

#define BATCH 32
#define C_CH  2048
#define N_SP  1152   // 48*24
#define MIDC  128

// ---------------- scratch (device globals; no allocation allowed) ----------------
__device__ __align__(128) float  g_attn[(size_t)BATCH * N_SP * N_SP];    // logits [b][i][j] f32
__device__ __align__(128) __half g_attn16[(size_t)BATCH * N_SP * N_SP];  // softmax [b][i][j] fp16
__device__ __align__(128) __half g_Wh[2][(size_t)MIDC * C_CH];           // fp16 hi of 2^13*W
__device__ __align__(128) __half g_Wl[2][(size_t)MIDC * C_CH];           // fp16 lo
__device__ __align__(128) __half g_qh[(size_t)BATCH * N_SP * MIDC];      // split(2^6 q) [n][m]
__device__ __align__(128) __half g_ql[(size_t)BATCH * N_SP * MIDC];
__device__ __align__(128) __half g_kh[(size_t)BATCH * N_SP * MIDC];      // split(2^6 k) [n][m]
__device__ __align__(128) __half g_kl[(size_t)BATCH * N_SP * MIDC];

// ---------------- helpers ----------------
__device__ __forceinline__ void split_h16(float x, __half& h, __half& l) {
    h = __float2half_rn(x);
    l = __float2half_rn(x - __half2float(h));
}
__device__ __forceinline__ void cp_async16(void* smem, const void* gmem) {
    uint32_t s = (uint32_t)__cvta_generic_to_shared(smem);
    asm volatile("cp.async.cg.shared.global [%0], [%1], 16;" :: "r"(s), "l"(gmem));
}
__device__ __forceinline__ void cp_commit() {
    asm volatile("cp.async.commit_group;" ::: "memory");
}
template <int NN>
__device__ __forceinline__ void cp_wait() {
    asm volatile("cp.async.wait_group %0;" :: "n"(NN) : "memory");
}
__device__ __forceinline__ void mma_f16(float c[4], const uint32_t a[4], const uint32_t b[2]) {
    asm volatile(
        "mma.sync.aligned.m16n8k16.row.col.f32.f16.f16.f32 "
        "{%0,%1,%2,%3}, {%4,%5,%6,%7}, {%8,%9}, {%0,%1,%2,%3};"
        : "+f"(c[0]), "+f"(c[1]), "+f"(c[2]), "+f"(c[3])
        : "r"(a[0]), "r"(a[1]), "r"(a[2]), "r"(a[3]), "r"(b[0]), "r"(b[1]));
}
__device__ __forceinline__ void ldsm_x4(uint32_t& r0, uint32_t& r1, uint32_t& r2, uint32_t& r3,
                                        uint32_t saddr) {
    asm volatile("ldmatrix.sync.aligned.m8n8.x4.shared.b16 {%0,%1,%2,%3}, [%4];"
                 : "=r"(r0), "=r"(r1), "=r"(r2), "=r"(r3) : "r"(saddr));
}
__device__ __forceinline__ void ldsm_x4_t(uint32_t& r0, uint32_t& r1, uint32_t& r2, uint32_t& r3,
                                          uint32_t saddr) {
    asm volatile("ldmatrix.sync.aligned.m8n8.x4.trans.shared.b16 {%0,%1,%2,%3}, [%4];"
                 : "=r"(r0), "=r"(r1), "=r"(r2), "=r"(r3) : "r"(saddr));
}

// ---- shared geometry ----
#define K1A_T 5120                       // halves per A tile (W hi or lo) [128][40]
#define K1B_T 4352                       // halves per B tile (x hi or lo) [32][136]
#define K1_STG (2 * K1A_T + 2 * K1B_T)
#define K1_SMEM (2 * K1_STG * 2)         // 75776 B
// K2a (Q-resident): Q tiles [128][136] hi+lo resident; K stages [128][136] hi+lo x2.
#define Q_T   (128 * 136)                // 17408 halves per tile
#define K2_QOFF 0
#define K2_KOFF (2 * Q_T)
#define K2_STG  (2 * Q_T)
#define K2_SMEM ((2 * Q_T + 2 * K2_STG) * 2)   // 208896 B
#define K3A_T 5120
#define K3B_T 4352
#define K3_STG (K3A_T + K3B_T)
#define K3_SMEM (2 * K3_STG * 2)         // 37888 B

// ============================================================================
// K0a: split 2^13*W into fp16 hi/lo (tiny).
// ============================================================================
__global__ void k0_splitW(const float* __restrict__ Wq, const float* __restrict__ Wk)
{
    const int i = blockIdx.x * 256 + threadIdx.x;
    if (i >= MIDC * C_CH) return;
    __half h, l;
    split_h16(Wq[i] * 8192.0f, h, l);
    g_Wh[0][i] = h; g_Wl[0][i] = l;
    split_h16(Wk[i] * 8192.0f, h, l);
    g_Wh[1][i] = h; g_Wl[1][i] = l;
}

// ============================================================================
// K1: projections via split-fp16 (3-term) mma m16n8k16. (unchanged)
// ============================================================================
__global__ __launch_bounds__(128, 2) void k1_proj(const float* __restrict__ feat)
{
    const int nblk = blockIdx.x;
    const int mblk = blockIdx.y;
    const int b    = blockIdx.z;
    const __half* Wh = g_Wh[mblk];
    const __half* Wl = g_Wl[mblk];
    const float*  X  = feat + (size_t)b * C_CH * N_SP;

    extern __shared__ __half smemh[];
    const uint32_t sb = (uint32_t)__cvta_generic_to_shared(smemh);

    const int tid  = threadIdx.x;
    const int warp = tid >> 5, lane = tid & 31;
    const int wm = warp >> 1, wn = warp & 1;
    const int g = lane >> 2, tig = lane & 3;
    const int n0 = nblk * 128;

    const uint32_t aRow = lane & 15;
    const uint32_t aCol = (lane >> 4) << 3;
    const uint32_t tKrow = (lane & 7) + (((lane >> 3) & 1) << 3);
    const uint32_t tNcol = (lane >> 4) << 3;

    float acc[4][8][4] = {};
    float4 xb[8];

    auto ldgB = [&](int kt) {
        const int k0 = kt * 32;
        #pragma unroll
        for (int it = 0; it < 8; it++) {
            int id  = tid + it * 128;
            int row = id >> 5;
            int nc  = (id & 31) * 4;
            xb[it] = *(const float4*)(X + (size_t)(k0 + row) * N_SP + n0 + nc);
        }
    };
    auto stsB = [&](int buf) {
        __half* st = smemh + buf * K1_STG + 2 * K1A_T;
        #pragma unroll
        for (int it = 0; it < 8; it++) {
            int id  = tid + it * 128;
            int row = id >> 5;
            int nc  = (id & 31) * 4;
            __half h0, l0, h1, l1, h2, l2, h3, l3;
            split_h16(xb[it].x, h0, l0); split_h16(xb[it].y, h1, l1);
            split_h16(xb[it].z, h2, l2); split_h16(xb[it].w, h3, l3);
            __half* ph = st + row * 136 + nc;
            *(__half2*)(ph)     = __halves2half2(h0, h1);
            *(__half2*)(ph + 2) = __halves2half2(h2, h3);
            __half* pl = ph + K1B_T;
            *(__half2*)(pl)     = __halves2half2(l0, l1);
            *(__half2*)(pl + 2) = __halves2half2(l2, l3);
        }
    };
    auto ldA = [&](int kt, int buf) {
        const int k0 = kt * 32;
        __half* st = smemh + buf * K1_STG;
        #pragma unroll
        for (int it = 0; it < 4; it++) {
            int id  = tid + it * 128;
            int row = id >> 2;
            int ch  = (id & 3) * 8;
            cp_async16(st + row * 40 + ch,         Wh + (size_t)row * C_CH + k0 + ch);
            cp_async16(st + K1A_T + row * 40 + ch, Wl + (size_t)row * C_CH + k0 + ch);
        }
    };

    const int KT = C_CH / 32;   // 64
    ldgB(0);
    ldA(0, 0); cp_commit();
    stsB(0);
    ldgB(1);

    for (int kt = 0; kt < KT; kt++) {
        const int buf = kt & 1;
        cp_wait<0>();
        __syncthreads();
        if (kt + 1 < KT) { ldA(kt + 1, buf ^ 1); cp_commit(); }

        const uint32_t stg  = sb + buf * (K1_STG * 2);
        const uint32_t stgB = stg + 2 * K1A_T * 2;
        #pragma unroll
        for (int ks = 0; ks < 2; ks++) {
            const int kb = ks * 16;
            uint32_t bh[8][2], bl[8][2];
            #pragma unroll
            for (int fnp = 0; fnp < 4; fnp++) {
                uint32_t ad = stgB + ((kb + tKrow) * 136 + wn * 64 + fnp * 16 + tNcol) * 2;
                ldsm_x4_t(bh[fnp * 2][0], bh[fnp * 2][1],
                          bh[fnp * 2 + 1][0], bh[fnp * 2 + 1][1], ad);
                ldsm_x4_t(bl[fnp * 2][0], bl[fnp * 2][1],
                          bl[fnp * 2 + 1][0], bl[fnp * 2 + 1][1], ad + K1B_T * 2);
            }
            #pragma unroll
            for (int fm = 0; fm < 4; fm++) {
                uint32_t ad = stg + ((wm * 64 + fm * 16 + aRow) * 40 + kb + aCol) * 2;
                uint32_t ah[4], al[4];
                ldsm_x4(ah[0], ah[1], ah[2], ah[3], ad);
                ldsm_x4(al[0], al[1], al[2], al[3], ad + K1A_T * 2);
                #pragma unroll
                for (int fn = 0; fn < 8; fn++) {
                    mma_f16(acc[fm][fn], ah, bh[fn]);
                    mma_f16(acc[fm][fn], al, bh[fn]);
                    mma_f16(acc[fm][fn], ah, bl[fn]);
                }
            }
        }

        if (kt + 1 < KT) {
            stsB(buf ^ 1);
            if (kt + 2 < KT) ldgB(kt + 2);
        }
    }

    __half* oh = (mblk == 0 ? g_qh : g_kh) + (size_t)b * N_SP * MIDC;
    __half* ol = (mblk == 0 ? g_ql : g_kl) + (size_t)b * N_SP * MIDC;
    #pragma unroll
    for (int fm = 0; fm < 4; fm++) {
        #pragma unroll
        for (int fn = 0; fn < 8; fn++) {
            int m = wm * 64 + fm * 16 + g;
            int n = n0 + wn * 64 + fn * 8 + tig * 2;
            #pragma unroll
            for (int e = 0; e < 4; e++) {
                int mm = m + (e >> 1) * 8;
                int nn = n + (e & 1);
                float v = acc[fm][fn][e] * 0.0078125f;
                __half h, l;
                split_h16(v, h, l);
                oh[(size_t)nn * MIDC + mm] = h;
                ol[(size_t)nn * MIDC + mm] = l;
            }
        }
    }
}

// ============================================================================
// K2a: logits, Q-resident persistent-j. (unchanged)
// ============================================================================
__global__ __launch_bounds__(256, 1) void k2_logits(void)
{
    const int iblk = blockIdx.x;
    const int b    = blockIdx.y;
    const __half* Qh = g_qh + ((size_t)b * N_SP + iblk * 128) * MIDC;
    const __half* Ql = g_ql + ((size_t)b * N_SP + iblk * 128) * MIDC;
    const __half* Kh = g_kh + (size_t)b * N_SP * MIDC;
    const __half* Kl = g_kl + (size_t)b * N_SP * MIDC;
    float* L = g_attn + (size_t)b * N_SP * N_SP;

    extern __shared__ __half smemh[];
    const uint32_t sb = (uint32_t)__cvta_generic_to_shared(smemh);

    const int tid  = threadIdx.x;
    const int warp = tid >> 5, lane = tid & 31;
    const int wm = warp >> 2, wn = warp & 3;
    const int g = lane >> 2, tig = lane & 3;
    const int i0 = iblk * 128;

    const uint32_t aRow = lane & 15;
    const uint32_t aCol = (lane >> 4) << 3;
    const uint32_t bRow = (lane & 7) + ((lane >> 4) << 3);
    const uint32_t bCol = ((lane >> 3) & 1) << 3;

    {
        __half* st = smemh + K2_QOFF;
        #pragma unroll
        for (int it = 0; it < 8; it++) {
            int id  = tid + it * 256;
            int row = id >> 4;
            int ch  = (id & 15) * 8;
            cp_async16(st + row * 136 + ch,       Qh + (size_t)row * MIDC + ch);
            cp_async16(st + Q_T + row * 136 + ch, Ql + (size_t)row * MIDC + ch);
        }
        cp_commit();
    }
    auto ldK = [&](int jb, int buf) {
        __half* st = smemh + K2_KOFF + buf * K2_STG;
        const __half* kh = Kh + (size_t)jb * 128 * MIDC;
        const __half* kl = Kl + (size_t)jb * 128 * MIDC;
        #pragma unroll
        for (int it = 0; it < 8; it++) {
            int id  = tid + it * 256;
            int row = id >> 4;
            int ch  = (id & 15) * 8;
            cp_async16(st + row * 136 + ch,       kh + (size_t)row * MIDC + ch);
            cp_async16(st + Q_T + row * 136 + ch, kl + (size_t)row * MIDC + ch);
        }
        cp_commit();
    };

    ldK(0, 0);

    const float s = 2.44140625e-4f;   // 2^-12
    for (int jb = 0; jb < 9; jb++) {
        const int buf = jb & 1;
        cp_wait<0>();
        __syncthreads();
        if (jb + 1 < 9) ldK(jb + 1, buf ^ 1);

        const uint32_t stgQ = sb + K2_QOFF * 2;
        const uint32_t stgK = sb + (K2_KOFF + buf * K2_STG) * 2;

        float acc[4][4][4] = {};
        #pragma unroll
        for (int ks = 0; ks < 8; ks++) {
            const int kb = ks * 16;
            uint32_t bh[4][2], bl[4][2];
            #pragma unroll
            for (int fnp = 0; fnp < 2; fnp++) {
                uint32_t ad = stgK + ((wn * 32 + fnp * 16 + bRow) * 136 + kb + bCol) * 2;
                ldsm_x4(bh[fnp * 2][0], bh[fnp * 2][1], bh[fnp * 2 + 1][0], bh[fnp * 2 + 1][1], ad);
                ldsm_x4(bl[fnp * 2][0], bl[fnp * 2][1], bl[fnp * 2 + 1][0], bl[fnp * 2 + 1][1],
                        ad + Q_T * 2);
            }
            #pragma unroll
            for (int fm = 0; fm < 4; fm++) {
                uint32_t ad = stgQ + ((wm * 64 + fm * 16 + aRow) * 136 + kb + aCol) * 2;
                uint32_t ah[4], al[4];
                ldsm_x4(ah[0], ah[1], ah[2], ah[3], ad);
                ldsm_x4(al[0], al[1], al[2], al[3], ad + Q_T * 2);
                #pragma unroll
                for (int fn = 0; fn < 4; fn++) {
                    mma_f16(acc[fm][fn], ah, bh[fn]);
                    mma_f16(acc[fm][fn], al, bh[fn]);
                    mma_f16(acc[fm][fn], ah, bl[fn]);
                }
            }
        }

        const int j0 = jb * 128;
        #pragma unroll
        for (int fm = 0; fm < 4; fm++) {
            #pragma unroll
            for (int fn = 0; fn < 4; fn++) {
                int ii  = i0 + wm * 64 + fm * 16 + g;
                int col = j0 + wn * 32 + fn * 8 + tig * 2;
                *(float2*)(L + (size_t)ii * N_SP + col) =
                    make_float2(acc[fm][fn][0] * s, acc[fm][fn][1] * s);
                *(float2*)(L + (size_t)(ii + 8) * N_SP + col) =
                    make_float2(acc[fm][fn][2] * s, acc[fm][fn][3] * s);
            }
        }
    }
}

// ============================================================================
// K2b: row softmax (length 1152), one warp per row, float4 IO. (unchanged)
// ============================================================================
__global__ void k2_softmax()
{
    const int row  = blockIdx.x * 8 + (threadIdx.x >> 5);
    const int lane = threadIdx.x & 31;
    const float* r   = g_attn   + (size_t)row * N_SP;
    __half*      r16 = g_attn16 + (size_t)row * N_SP;

    float4 f[9];
    float mx = -1e30f;
    #pragma unroll
    for (int t = 0; t < 9; t++) {
        f[t] = *(const float4*)(r + lane * 4 + t * 128);
        mx = fmaxf(mx, fmaxf(fmaxf(f[t].x, f[t].y), fmaxf(f[t].z, f[t].w)));
    }
    #pragma unroll
    for (int o = 16; o > 0; o >>= 1) mx = fmaxf(mx, __shfl_xor_sync(0xffffffffu, mx, o));

    float s = 0.0f;
    #pragma unroll
    for (int t = 0; t < 9; t++) {
        f[t].x = __expf(f[t].x - mx); f[t].y = __expf(f[t].y - mx);
        f[t].z = __expf(f[t].z - mx); f[t].w = __expf(f[t].w - mx);
        s += (f[t].x + f[t].y) + (f[t].z + f[t].w);
    }
    #pragma unroll
    for (int o = 16; o > 0; o >>= 1) s += __shfl_xor_sync(0xffffffffu, s, o);

    const float inv = 1.0f / s;
    #pragma unroll
    for (int t = 0; t < 9; t++) {
        __half2 h0 = __floats2half2_rn(f[t].x * inv, f[t].y * inv);
        __half2 h1 = __floats2half2_rn(f[t].z * inv, f[t].w * inv);
        *(__half2*)(r16 + lane * 4 + t * 128)     = h0;
        *(__half2*)(r16 + lane * 4 + t * 128 + 2) = h1;
    }
}

// ============================================================================
// K3: refined = cam @ attn via FP16 mma; cam converted in-kernel.
// SINGLE CHANGE THIS ROUND: occupancy 2 -> 3 CTAs/SM (12 warps/SM) to hide
// per-iteration sync/STS latency; regs capped ~170 (xa may spill to L1-local,
// hidden under MMA block).
// ============================================================================
__global__ __launch_bounds__(128, 3) void k3_refined(
    const float* __restrict__ cam,
    const float* __restrict__ alphaPtr,
    float* __restrict__ out)
{
    const int jblk = blockIdx.x;
    const int cblk = blockIdx.y;
    const int b    = blockIdx.z;

    const __half* Bhg = g_attn16 + (size_t)b * N_SP * N_SP;
    const float*  Af  = cam      + (size_t)b * C_CH * N_SP;

    extern __shared__ __half smemh[];
    const uint32_t sb = (uint32_t)__cvta_generic_to_shared(smemh);

    const int tid  = threadIdx.x;
    const int warp = tid >> 5, lane = tid & 31;
    const int wm = warp >> 1, wn = warp & 1;
    const int g = lane >> 2, tig = lane & 3;
    const int c0 = cblk * 128, j0 = jblk * 128;

    const uint32_t aRow = lane & 15;
    const uint32_t aCol = (lane >> 4) << 3;
    const uint32_t tKrow = (lane & 7) + (((lane >> 3) & 1) << 3);
    const uint32_t tNcol = (lane >> 4) << 3;

    float acc[4][8][4] = {};
    float4 xa[8];

    auto ldgA = [&](int kt) {
        const int k0 = kt * 32;
        #pragma unroll
        for (int it = 0; it < 8; it++) {
            int id  = tid + it * 128;
            int row = id >> 3;
            int kc  = (id & 7) * 4;
            xa[it] = *(const float4*)(Af + (size_t)(c0 + row) * N_SP + k0 + kc);
        }
    };
    auto stsA = [&](int buf) {
        __half* st = smemh + buf * K3_STG;
        #pragma unroll
        for (int it = 0; it < 8; it++) {
            int id  = tid + it * 128;
            int row = id >> 3;
            int kc  = (id & 7) * 4;
            __half* p = st + row * 40 + kc;
            *(__half2*)(p)     = __floats2half2_rn(xa[it].x, xa[it].y);
            *(__half2*)(p + 2) = __floats2half2_rn(xa[it].z, xa[it].w);
        }
    };
    auto cpB = [&](int kt, int buf) {
        const int k0 = kt * 32;
        __half* st = smemh + buf * K3_STG + K3A_T;
        #pragma unroll
        for (int it = 0; it < 4; it++) {
            int id  = tid + it * 128;
            int row = id >> 4;
            int ch  = (id & 15) * 8;
            cp_async16(st + row * 136 + ch, Bhg + (size_t)(k0 + row) * N_SP + j0 + ch);
        }
    };

    const int KT = N_SP / 32;   // 36
    ldgA(0);
    cpB(0, 0); cp_commit();
    stsA(0);
    ldgA(1);

    for (int kt = 0; kt < KT; kt++) {
        const int buf = kt & 1;
        cp_wait<0>();
        __syncthreads();
        if (kt + 1 < KT) { cpB(kt + 1, buf ^ 1); cp_commit(); }

        const uint32_t stg  = sb + buf * (K3_STG * 2);
        const uint32_t stgB = stg + K3A_T * 2;
        #pragma unroll
        for (int ks = 0; ks < 2; ks++) {
            const int kb = ks * 16;
            uint32_t bfr[8][2];
            #pragma unroll
            for (int fnp = 0; fnp < 4; fnp++) {
                uint32_t ad = stgB + ((kb + tKrow) * 136 + wn * 64 + fnp * 16 + tNcol) * 2;
                ldsm_x4_t(bfr[fnp * 2][0], bfr[fnp * 2][1],
                          bfr[fnp * 2 + 1][0], bfr[fnp * 2 + 1][1], ad);
            }
            #pragma unroll
            for (int fm = 0; fm < 4; fm++) {
                uint32_t ad = stg + ((wm * 64 + fm * 16 + aRow) * 40 + kb + aCol) * 2;
                uint32_t afr[4];
                ldsm_x4(afr[0], afr[1], afr[2], afr[3], ad);
                #pragma unroll
                for (int fn = 0; fn < 8; fn++)
                    mma_f16(acc[fm][fn], afr, bfr[fn]);
            }
        }

        if (kt + 1 < KT) {
            stsA(buf ^ 1);
            if (kt + 2 < KT) ldgA(kt + 2);
        }
    }

    const float alpha = alphaPtr[0];
    const size_t base = (size_t)b * C_CH * N_SP;
    #pragma unroll
    for (int fm = 0; fm < 4; fm++) {
        #pragma unroll
        for (int fn = 0; fn < 8; fn++) {
            int mrow = c0 + wm * 64 + fm * 16 + g;
            int col  = j0 + wn * 64 + fn * 8 + tig * 2;
            const float2 cv0 = *(const float2*)(Af + (size_t)mrow * N_SP + col);
            const float2 cv1 = *(const float2*)(Af + (size_t)(mrow + 8) * N_SP + col);
            float2 r0, r1;
            r0.x = fmaf(alpha, acc[fm][fn][0], cv0.x);
            r0.y = fmaf(alpha, acc[fm][fn][1], cv0.y);
            r1.x = fmaf(alpha, acc[fm][fn][2], cv1.x);
            r1.y = fmaf(alpha, acc[fm][fn][3], cv1.y);
            *(float2*)(out + base + (size_t)mrow * N_SP + col)       = r0;
            *(float2*)(out + base + (size_t)(mrow + 8) * N_SP + col) = r1;
        }
    }
}

// ============================================================================
extern "C" void kernel_launch(void* const* d_in, const int* in_sizes, int n_in,
                              void* d_out, int out_size)
{
    (void)in_sizes; (void)n_in; (void)out_size;
    const float* feat  = (const float*)d_in[0];
    const float* cam   = (const float*)d_in[1];
    const float* Wq    = (const float*)d_in[2];
    const float* Wk    = (const float*)d_in[3];
    const float* alpha = (const float*)d_in[4];
    float* out = (float*)d_out;

    cudaFuncSetAttribute(k1_proj,    cudaFuncAttributeMaxDynamicSharedMemorySize, K1_SMEM);
    cudaFuncSetAttribute(k2_logits,  cudaFuncAttributeMaxDynamicSharedMemorySize, K2_SMEM);
    cudaFuncSetAttribute(k3_refined, cudaFuncAttributeMaxDynamicSharedMemorySize, K3_SMEM);

    k0_splitW<<<(MIDC * C_CH + 255) / 256, 256>>>(Wq, Wk);
    k1_proj<<<dim3(9, 2, BATCH), 128, K1_SMEM>>>(feat);
    k2_logits<<<dim3(9, BATCH), 256, K2_SMEM>>>();
    k2_softmax<<<(BATCH * N_SP) / 8, 256>>>();
    k3_refined<<<dim3(9, 16, BATCH), 128, K3_SMEM>>>(cam, alpha, out);
}

// round 15
// speedup vs baseline: 1.3878x; 1.3878x over previous
#include <cuda_runtime.h>
#include <cuda_fp16.h>
#include <cstdint>
#include <cstddef>

#define BATCH 32
#define C_CH  2048
#define N_SP  1152   // 48*24
#define MIDC  128

// ---------------- scratch (device globals; no allocation allowed) ----------------
__device__ __align__(128) float  g_attn[(size_t)BATCH * N_SP * N_SP];    // logits [b][i][j] f32
__device__ __align__(128) __half g_attn16[(size_t)BATCH * N_SP * N_SP];  // softmax [b][i][j] fp16
__device__ __align__(128) __half g_Wh[2][(size_t)MIDC * C_CH];           // fp16 hi of 2^13*W
__device__ __align__(128) __half g_Wl[2][(size_t)MIDC * C_CH];           // fp16 lo
__device__ __align__(128) __half g_qh[(size_t)BATCH * N_SP * MIDC];      // split(2^6 q) [n][m]
__device__ __align__(128) __half g_ql[(size_t)BATCH * N_SP * MIDC];
__device__ __align__(128) __half g_kh[(size_t)BATCH * N_SP * MIDC];      // split(2^6 k) [n][m]
__device__ __align__(128) __half g_kl[(size_t)BATCH * N_SP * MIDC];

// ---------------- helpers ----------------
__device__ __forceinline__ void split_h16(float x, __half& h, __half& l) {
    h = __float2half_rn(x);
    l = __float2half_rn(x - __half2float(h));
}
__device__ __forceinline__ void cp_async16(void* smem, const void* gmem) {
    uint32_t s = (uint32_t)__cvta_generic_to_shared(smem);
    asm volatile("cp.async.cg.shared.global [%0], [%1], 16;" :: "r"(s), "l"(gmem));
}
__device__ __forceinline__ void cp_commit() {
    asm volatile("cp.async.commit_group;" ::: "memory");
}
template <int NN>
__device__ __forceinline__ void cp_wait() {
    asm volatile("cp.async.wait_group %0;" :: "n"(NN) : "memory");
}
__device__ __forceinline__ void mma_f16(float c[4], const uint32_t a[4], const uint32_t b[2]) {
    asm volatile(
        "mma.sync.aligned.m16n8k16.row.col.f32.f16.f16.f32 "
        "{%0,%1,%2,%3}, {%4,%5,%6,%7}, {%8,%9}, {%0,%1,%2,%3};"
        : "+f"(c[0]), "+f"(c[1]), "+f"(c[2]), "+f"(c[3])
        : "r"(a[0]), "r"(a[1]), "r"(a[2]), "r"(a[3]), "r"(b[0]), "r"(b[1]));
}
__device__ __forceinline__ void ldsm_x4(uint32_t& r0, uint32_t& r1, uint32_t& r2, uint32_t& r3,
                                        uint32_t saddr) {
    asm volatile("ldmatrix.sync.aligned.m8n8.x4.shared.b16 {%0,%1,%2,%3}, [%4];"
                 : "=r"(r0), "=r"(r1), "=r"(r2), "=r"(r3) : "r"(saddr));
}
__device__ __forceinline__ void ldsm_x4_t(uint32_t& r0, uint32_t& r1, uint32_t& r2, uint32_t& r3,
                                          uint32_t saddr) {
    asm volatile("ldmatrix.sync.aligned.m8n8.x4.trans.shared.b16 {%0,%1,%2,%3}, [%4];"
                 : "=r"(r0), "=r"(r1), "=r"(r2), "=r"(r3) : "r"(saddr));
}

// ---- shared geometry ----
#define K1A_T 5120                       // halves per A tile (W hi or lo) [128][40]
#define K1B_T 4352                       // halves per B tile (x hi or lo) [32][136]
#define K1_STG (2 * K1A_T + 2 * K1B_T)
#define K1_SMEM (2 * K1_STG * 2)         // 75776 B
// K2a (Q-resident): Q tiles [128][136] hi+lo resident; K stages [128][136] hi+lo x2.
#define Q_T   (128 * 136)                // 17408 halves per tile
#define K2_QOFF 0
#define K2_KOFF (2 * Q_T)
#define K2_STG  (2 * Q_T)
#define K2_SMEM ((2 * Q_T + 2 * K2_STG) * 2)   // 208896 B
#define K3A_T 5120
#define K3B_T 4352
#define K3_STG (K3A_T + K3B_T)
#define K3_SMEM (2 * K3_STG * 2)         // 37888 B

// ============================================================================
// K0a: split 2^13*W into fp16 hi/lo (tiny).
// ============================================================================
__global__ void k0_splitW(const float* __restrict__ Wq, const float* __restrict__ Wk)
{
    const int i = blockIdx.x * 256 + threadIdx.x;
    if (i >= MIDC * C_CH) return;
    __half h, l;
    split_h16(Wq[i] * 8192.0f, h, l);
    g_Wh[0][i] = h; g_Wl[0][i] = l;
    split_h16(Wk[i] * 8192.0f, h, l);
    g_Wh[1][i] = h; g_Wl[1][i] = l;
}

// ============================================================================
// K1: projections via split-fp16 (3-term) mma m16n8k16.
// Block 128x128, 4 warps (2x2) of 64x64, BK=32, one-barrier double-buffer.
// ============================================================================
__global__ __launch_bounds__(128, 2) void k1_proj(const float* __restrict__ feat)
{
    const int nblk = blockIdx.x;
    const int mblk = blockIdx.y;
    const int b    = blockIdx.z;
    const __half* Wh = g_Wh[mblk];
    const __half* Wl = g_Wl[mblk];
    const float*  X  = feat + (size_t)b * C_CH * N_SP;

    extern __shared__ __half smemh[];
    const uint32_t sb = (uint32_t)__cvta_generic_to_shared(smemh);

    const int tid  = threadIdx.x;
    const int warp = tid >> 5, lane = tid & 31;
    const int wm = warp >> 1, wn = warp & 1;
    const int g = lane >> 2, tig = lane & 3;
    const int n0 = nblk * 128;

    const uint32_t aRow = lane & 15;
    const uint32_t aCol = (lane >> 4) << 3;
    const uint32_t tKrow = (lane & 7) + (((lane >> 3) & 1) << 3);
    const uint32_t tNcol = (lane >> 4) << 3;

    float acc[4][8][4] = {};
    float4 xb[8];

    auto ldgB = [&](int kt) {
        const int k0 = kt * 32;
        #pragma unroll
        for (int it = 0; it < 8; it++) {
            int id  = tid + it * 128;
            int row = id >> 5;
            int nc  = (id & 31) * 4;
            xb[it] = *(const float4*)(X + (size_t)(k0 + row) * N_SP + n0 + nc);
        }
    };
    auto stsB = [&](int buf) {
        __half* st = smemh + buf * K1_STG + 2 * K1A_T;
        #pragma unroll
        for (int it = 0; it < 8; it++) {
            int id  = tid + it * 128;
            int row = id >> 5;
            int nc  = (id & 31) * 4;
            __half h0, l0, h1, l1, h2, l2, h3, l3;
            split_h16(xb[it].x, h0, l0); split_h16(xb[it].y, h1, l1);
            split_h16(xb[it].z, h2, l2); split_h16(xb[it].w, h3, l3);
            __half* ph = st + row * 136 + nc;
            *(__half2*)(ph)     = __halves2half2(h0, h1);
            *(__half2*)(ph + 2) = __halves2half2(h2, h3);
            __half* pl = ph + K1B_T;
            *(__half2*)(pl)     = __halves2half2(l0, l1);
            *(__half2*)(pl + 2) = __halves2half2(l2, l3);
        }
    };
    auto ldA = [&](int kt, int buf) {
        const int k0 = kt * 32;
        __half* st = smemh + buf * K1_STG;
        #pragma unroll
        for (int it = 0; it < 4; it++) {
            int id  = tid + it * 128;
            int row = id >> 2;
            int ch  = (id & 3) * 8;
            cp_async16(st + row * 40 + ch,         Wh + (size_t)row * C_CH + k0 + ch);
            cp_async16(st + K1A_T + row * 40 + ch, Wl + (size_t)row * C_CH + k0 + ch);
        }
    };

    const int KT = C_CH / 32;   // 64
    ldgB(0);
    ldA(0, 0); cp_commit();
    stsB(0);
    ldgB(1);

    for (int kt = 0; kt < KT; kt++) {
        const int buf = kt & 1;
        cp_wait<0>();
        __syncthreads();
        if (kt + 1 < KT) { ldA(kt + 1, buf ^ 1); cp_commit(); }

        const uint32_t stg  = sb + buf * (K1_STG * 2);
        const uint32_t stgB = stg + 2 * K1A_T * 2;
        #pragma unroll
        for (int ks = 0; ks < 2; ks++) {
            const int kb = ks * 16;
            uint32_t bh[8][2], bl[8][2];
            #pragma unroll
            for (int fnp = 0; fnp < 4; fnp++) {
                uint32_t ad = stgB + ((kb + tKrow) * 136 + wn * 64 + fnp * 16 + tNcol) * 2;
                ldsm_x4_t(bh[fnp * 2][0], bh[fnp * 2][1],
                          bh[fnp * 2 + 1][0], bh[fnp * 2 + 1][1], ad);
                ldsm_x4_t(bl[fnp * 2][0], bl[fnp * 2][1],
                          bl[fnp * 2 + 1][0], bl[fnp * 2 + 1][1], ad + K1B_T * 2);
            }
            #pragma unroll
            for (int fm = 0; fm < 4; fm++) {
                uint32_t ad = stg + ((wm * 64 + fm * 16 + aRow) * 40 + kb + aCol) * 2;
                uint32_t ah[4], al[4];
                ldsm_x4(ah[0], ah[1], ah[2], ah[3], ad);
                ldsm_x4(al[0], al[1], al[2], al[3], ad + K1A_T * 2);
                #pragma unroll
                for (int fn = 0; fn < 8; fn++) {
                    mma_f16(acc[fm][fn], ah, bh[fn]);
                    mma_f16(acc[fm][fn], al, bh[fn]);
                    mma_f16(acc[fm][fn], ah, bl[fn]);
                }
            }
        }

        if (kt + 1 < KT) {
            stsB(buf ^ 1);
            if (kt + 2 < KT) ldgB(kt + 2);
        }
    }

    __half* oh = (mblk == 0 ? g_qh : g_kh) + (size_t)b * N_SP * MIDC;
    __half* ol = (mblk == 0 ? g_ql : g_kl) + (size_t)b * N_SP * MIDC;
    #pragma unroll
    for (int fm = 0; fm < 4; fm++) {
        #pragma unroll
        for (int fn = 0; fn < 8; fn++) {
            int m = wm * 64 + fm * 16 + g;
            int n = n0 + wn * 64 + fn * 8 + tig * 2;
            #pragma unroll
            for (int e = 0; e < 4; e++) {
                int mm = m + (e >> 1) * 8;
                int nn = n + (e & 1);
                float v = acc[fm][fn][e] * 0.0078125f;
                __half h, l;
                split_h16(v, h, l);
                oh[(size_t)nn * MIDC + mm] = h;
                ol[(size_t)nn * MIDC + mm] = l;
            }
        }
    }
}

// ============================================================================
// K2a: logits, Q-resident persistent-j. grid (9 iblk, 32 b), 256 thr, 1 CTA/SM.
// ============================================================================
__global__ __launch_bounds__(256, 1) void k2_logits(void)
{
    const int iblk = blockIdx.x;
    const int b    = blockIdx.y;
    const __half* Qh = g_qh + ((size_t)b * N_SP + iblk * 128) * MIDC;
    const __half* Ql = g_ql + ((size_t)b * N_SP + iblk * 128) * MIDC;
    const __half* Kh = g_kh + (size_t)b * N_SP * MIDC;
    const __half* Kl = g_kl + (size_t)b * N_SP * MIDC;
    float* L = g_attn + (size_t)b * N_SP * N_SP;

    extern __shared__ __half smemh[];
    const uint32_t sb = (uint32_t)__cvta_generic_to_shared(smemh);

    const int tid  = threadIdx.x;
    const int warp = tid >> 5, lane = tid & 31;
    const int wm = warp >> 2, wn = warp & 3;
    const int g = lane >> 2, tig = lane & 3;
    const int i0 = iblk * 128;

    const uint32_t aRow = lane & 15;
    const uint32_t aCol = (lane >> 4) << 3;
    const uint32_t bRow = (lane & 7) + ((lane >> 4) << 3);
    const uint32_t bCol = ((lane >> 3) & 1) << 3;

    {
        __half* st = smemh + K2_QOFF;
        #pragma unroll
        for (int it = 0; it < 8; it++) {
            int id  = tid + it * 256;
            int row = id >> 4;
            int ch  = (id & 15) * 8;
            cp_async16(st + row * 136 + ch,       Qh + (size_t)row * MIDC + ch);
            cp_async16(st + Q_T + row * 136 + ch, Ql + (size_t)row * MIDC + ch);
        }
        cp_commit();
    }
    auto ldK = [&](int jb, int buf) {
        __half* st = smemh + K2_KOFF + buf * K2_STG;
        const __half* kh = Kh + (size_t)jb * 128 * MIDC;
        const __half* kl = Kl + (size_t)jb * 128 * MIDC;
        #pragma unroll
        for (int it = 0; it < 8; it++) {
            int id  = tid + it * 256;
            int row = id >> 4;
            int ch  = (id & 15) * 8;
            cp_async16(st + row * 136 + ch,       kh + (size_t)row * MIDC + ch);
            cp_async16(st + Q_T + row * 136 + ch, kl + (size_t)row * MIDC + ch);
        }
        cp_commit();
    };

    ldK(0, 0);

    const float s = 2.44140625e-4f;   // 2^-12
    for (int jb = 0; jb < 9; jb++) {
        const int buf = jb & 1;
        cp_wait<0>();
        __syncthreads();
        if (jb + 1 < 9) ldK(jb + 1, buf ^ 1);

        const uint32_t stgQ = sb + K2_QOFF * 2;
        const uint32_t stgK = sb + (K2_KOFF + buf * K2_STG) * 2;

        float acc[4][4][4] = {};
        #pragma unroll
        for (int ks = 0; ks < 8; ks++) {
            const int kb = ks * 16;
            uint32_t bh[4][2], bl[4][2];
            #pragma unroll
            for (int fnp = 0; fnp < 2; fnp++) {
                uint32_t ad = stgK + ((wn * 32 + fnp * 16 + bRow) * 136 + kb + bCol) * 2;
                ldsm_x4(bh[fnp * 2][0], bh[fnp * 2][1], bh[fnp * 2 + 1][0], bh[fnp * 2 + 1][1], ad);
                ldsm_x4(bl[fnp * 2][0], bl[fnp * 2][1], bl[fnp * 2 + 1][0], bl[fnp * 2 + 1][1],
                        ad + Q_T * 2);
            }
            #pragma unroll
            for (int fm = 0; fm < 4; fm++) {
                uint32_t ad = stgQ + ((wm * 64 + fm * 16 + aRow) * 136 + kb + aCol) * 2;
                uint32_t ah[4], al[4];
                ldsm_x4(ah[0], ah[1], ah[2], ah[3], ad);
                ldsm_x4(al[0], al[1], al[2], al[3], ad + Q_T * 2);
                #pragma unroll
                for (int fn = 0; fn < 4; fn++) {
                    mma_f16(acc[fm][fn], ah, bh[fn]);
                    mma_f16(acc[fm][fn], al, bh[fn]);
                    mma_f16(acc[fm][fn], ah, bl[fn]);
                }
            }
        }

        const int j0 = jb * 128;
        #pragma unroll
        for (int fm = 0; fm < 4; fm++) {
            #pragma unroll
            for (int fn = 0; fn < 4; fn++) {
                int ii  = i0 + wm * 64 + fm * 16 + g;
                int col = j0 + wn * 32 + fn * 8 + tig * 2;
                *(float2*)(L + (size_t)ii * N_SP + col) =
                    make_float2(acc[fm][fn][0] * s, acc[fm][fn][1] * s);
                *(float2*)(L + (size_t)(ii + 8) * N_SP + col) =
                    make_float2(acc[fm][fn][2] * s, acc[fm][fn][3] * s);
            }
        }
    }
}

// ============================================================================
// K2b: row softmax (length 1152), one warp per row, float4 IO. f32 in, fp16 out.
// ============================================================================
__global__ void k2_softmax()
{
    const int row  = blockIdx.x * 8 + (threadIdx.x >> 5);
    const int lane = threadIdx.x & 31;
    const float* r   = g_attn   + (size_t)row * N_SP;
    __half*      r16 = g_attn16 + (size_t)row * N_SP;

    float4 f[9];
    float mx = -1e30f;
    #pragma unroll
    for (int t = 0; t < 9; t++) {
        f[t] = *(const float4*)(r + lane * 4 + t * 128);
        mx = fmaxf(mx, fmaxf(fmaxf(f[t].x, f[t].y), fmaxf(f[t].z, f[t].w)));
    }
    #pragma unroll
    for (int o = 16; o > 0; o >>= 1) mx = fmaxf(mx, __shfl_xor_sync(0xffffffffu, mx, o));

    float s = 0.0f;
    #pragma unroll
    for (int t = 0; t < 9; t++) {
        f[t].x = __expf(f[t].x - mx); f[t].y = __expf(f[t].y - mx);
        f[t].z = __expf(f[t].z - mx); f[t].w = __expf(f[t].w - mx);
        s += (f[t].x + f[t].y) + (f[t].z + f[t].w);
    }
    #pragma unroll
    for (int o = 16; o > 0; o >>= 1) s += __shfl_xor_sync(0xffffffffu, s, o);

    const float inv = 1.0f / s;
    #pragma unroll
    for (int t = 0; t < 9; t++) {
        __half2 h0 = __floats2half2_rn(f[t].x * inv, f[t].y * inv);
        __half2 h1 = __floats2half2_rn(f[t].z * inv, f[t].w * inv);
        *(__half2*)(r16 + lane * 4 + t * 128)     = h0;
        *(__half2*)(r16 + lane * 4 + t * 128 + 2) = h1;
    }
}

// ============================================================================
// K3: refined = cam @ attn via FP16 mma; cam converted in-kernel.
// Block 128x128, 4 warps (2m x 2n) of 64x64, BK=32, one-barrier double-buffer,
// 2 CTAs/SM (register wall: 3 CTAs/SM spills catastrophically — round 14).
// ============================================================================
__global__ __launch_bounds__(128, 2) void k3_refined(
    const float* __restrict__ cam,
    const float* __restrict__ alphaPtr,
    float* __restrict__ out)
{
    const int jblk = blockIdx.x;
    const int cblk = blockIdx.y;
    const int b    = blockIdx.z;

    const __half* Bhg = g_attn16 + (size_t)b * N_SP * N_SP;
    const float*  Af  = cam      + (size_t)b * C_CH * N_SP;

    extern __shared__ __half smemh[];
    const uint32_t sb = (uint32_t)__cvta_generic_to_shared(smemh);

    const int tid  = threadIdx.x;
    const int warp = tid >> 5, lane = tid & 31;
    const int wm = warp >> 1, wn = warp & 1;
    const int g = lane >> 2, tig = lane & 3;
    const int c0 = cblk * 128, j0 = jblk * 128;

    const uint32_t aRow = lane & 15;
    const uint32_t aCol = (lane >> 4) << 3;
    const uint32_t tKrow = (lane & 7) + (((lane >> 3) & 1) << 3);
    const uint32_t tNcol = (lane >> 4) << 3;

    float acc[4][8][4] = {};
    float4 xa[8];

    auto ldgA = [&](int kt) {
        const int k0 = kt * 32;
        #pragma unroll
        for (int it = 0; it < 8; it++) {
            int id  = tid + it * 128;
            int row = id >> 3;
            int kc  = (id & 7) * 4;
            xa[it] = *(const float4*)(Af + (size_t)(c0 + row) * N_SP + k0 + kc);
        }
    };
    auto stsA = [&](int buf) {
        __half* st = smemh + buf * K3_STG;
        #pragma unroll
        for (int it = 0; it < 8; it++) {
            int id  = tid + it * 128;
            int row = id >> 3;
            int kc  = (id & 7) * 4;
            __half* p = st + row * 40 + kc;
            *(__half2*)(p)     = __floats2half2_rn(xa[it].x, xa[it].y);
            *(__half2*)(p + 2) = __floats2half2_rn(xa[it].z, xa[it].w);
        }
    };
    auto cpB = [&](int kt, int buf) {
        const int k0 = kt * 32;
        __half* st = smemh + buf * K3_STG + K3A_T;
        #pragma unroll
        for (int it = 0; it < 4; it++) {
            int id  = tid + it * 128;
            int row = id >> 4;
            int ch  = (id & 15) * 8;
            cp_async16(st + row * 136 + ch, Bhg + (size_t)(k0 + row) * N_SP + j0 + ch);
        }
    };

    const int KT = N_SP / 32;   // 36
    ldgA(0);
    cpB(0, 0); cp_commit();
    stsA(0);
    ldgA(1);

    for (int kt = 0; kt < KT; kt++) {
        const int buf = kt & 1;
        cp_wait<0>();
        __syncthreads();
        if (kt + 1 < KT) { cpB(kt + 1, buf ^ 1); cp_commit(); }

        const uint32_t stg  = sb + buf * (K3_STG * 2);
        const uint32_t stgB = stg + K3A_T * 2;
        #pragma unroll
        for (int ks = 0; ks < 2; ks++) {
            const int kb = ks * 16;
            uint32_t bfr[8][2];
            #pragma unroll
            for (int fnp = 0; fnp < 4; fnp++) {
                uint32_t ad = stgB + ((kb + tKrow) * 136 + wn * 64 + fnp * 16 + tNcol) * 2;
                ldsm_x4_t(bfr[fnp * 2][0], bfr[fnp * 2][1],
                          bfr[fnp * 2 + 1][0], bfr[fnp * 2 + 1][1], ad);
            }
            #pragma unroll
            for (int fm = 0; fm < 4; fm++) {
                uint32_t ad = stg + ((wm * 64 + fm * 16 + aRow) * 40 + kb + aCol) * 2;
                uint32_t afr[4];
                ldsm_x4(afr[0], afr[1], afr[2], afr[3], ad);
                #pragma unroll
                for (int fn = 0; fn < 8; fn++)
                    mma_f16(acc[fm][fn], afr, bfr[fn]);
            }
        }

        if (kt + 1 < KT) {
            stsA(buf ^ 1);
            if (kt + 2 < KT) ldgA(kt + 2);
        }
    }

    const float alpha = alphaPtr[0];
    const size_t base = (size_t)b * C_CH * N_SP;
    #pragma unroll
    for (int fm = 0; fm < 4; fm++) {
        #pragma unroll
        for (int fn = 0; fn < 8; fn++) {
            int mrow = c0 + wm * 64 + fm * 16 + g;
            int col  = j0 + wn * 64 + fn * 8 + tig * 2;
            const float2 cv0 = *(const float2*)(Af + (size_t)mrow * N_SP + col);
            const float2 cv1 = *(const float2*)(Af + (size_t)(mrow + 8) * N_SP + col);
            float2 r0, r1;
            r0.x = fmaf(alpha, acc[fm][fn][0], cv0.x);
            r0.y = fmaf(alpha, acc[fm][fn][1], cv0.y);
            r1.x = fmaf(alpha, acc[fm][fn][2], cv1.x);
            r1.y = fmaf(alpha, acc[fm][fn][3], cv1.y);
            *(float2*)(out + base + (size_t)mrow * N_SP + col)       = r0;
            *(float2*)(out + base + (size_t)(mrow + 8) * N_SP + col) = r1;
        }
    }
}

// ============================================================================
extern "C" void kernel_launch(void* const* d_in, const int* in_sizes, int n_in,
                              void* d_out, int out_size)
{
    (void)in_sizes; (void)n_in; (void)out_size;
    const float* feat  = (const float*)d_in[0];
    const float* cam   = (const float*)d_in[1];
    const float* Wq    = (const float*)d_in[2];
    const float* Wk    = (const float*)d_in[3];
    const float* alpha = (const float*)d_in[4];
    float* out = (float*)d_out;

    cudaFuncSetAttribute(k1_proj,    cudaFuncAttributeMaxDynamicSharedMemorySize, K1_SMEM);
    cudaFuncSetAttribute(k2_logits,  cudaFuncAttributeMaxDynamicSharedMemorySize, K2_SMEM);
    cudaFuncSetAttribute(k3_refined, cudaFuncAttributeMaxDynamicSharedMemorySize, K3_SMEM);

    k0_splitW<<<(MIDC * C_CH + 255) / 256, 256>>>(Wq, Wk);
    k1_proj<<<dim3(9, 2, BATCH), 128, K1_SMEM>>>(feat);
    k2_logits<<<dim3(9, BATCH), 256, K2_SMEM>>>();
    k2_softmax<<<(BATCH * N_SP) / 8, 256>>>();
    k3_refined<<<dim3(9, 16, BATCH), 128, K3_SMEM>>>(cam, alpha, out);
}